// round 2
// baseline (speedup 1.0000x reference)
#include <cuda_runtime.h>
#include <cuda_bf16.h>
#include <cstdint>
#include <cmath>

// Problem constants (fixed by the dataset)
#define E_ 8
#define D_ 1024
#define H_ 4096
#define N_ 8192

// Tiling
#define BM 128
#define BN 64
#define BK 32
#define LD 40            // padded smem row stride (bf16 elems) -> conflict-free LDSM
#define NTHREADS 256

// 64MB bf16 scratch for the intermediate h = gelu(x@w1^T) * (x@w3^T)
__device__ __nv_bfloat16 g_hbuf[(size_t)N_ * H_];

// ---------------------------------------------------------------------------
// helpers
// ---------------------------------------------------------------------------
__device__ __forceinline__ uint32_t smem_u32(const void* p) {
    return (uint32_t)__cvta_generic_to_shared(p);
}

__device__ __forceinline__ void ldsm_x4(uint32_t* r, uint32_t addr) {
    asm volatile("ldmatrix.sync.aligned.m8n8.x4.shared.b16 {%0,%1,%2,%3}, [%4];\n"
                 : "=r"(r[0]), "=r"(r[1]), "=r"(r[2]), "=r"(r[3])
                 : "r"(addr));
}

__device__ __forceinline__ void ldsm_x2(uint32_t* r, uint32_t addr) {
    asm volatile("ldmatrix.sync.aligned.m8n8.x2.shared.b16 {%0,%1}, [%2];\n"
                 : "=r"(r[0]), "=r"(r[1])
                 : "r"(addr));
}

__device__ __forceinline__ void mma_bf16(float* c, const uint32_t* a, const uint32_t* b) {
    asm volatile("mma.sync.aligned.m16n8k16.row.col.f32.bf16.bf16.f32 "
                 "{%0,%1,%2,%3}, {%4,%5,%6,%7}, {%8,%9}, {%0,%1,%2,%3};\n"
                 : "+f"(c[0]), "+f"(c[1]), "+f"(c[2]), "+f"(c[3])
                 : "r"(a[0]), "r"(a[1]), "r"(a[2]), "r"(a[3]),
                   "r"(b[0]), "r"(b[1]));
}

// round-trip through bf16 (mimics XLA per-op bf16 rounding)
__device__ __forceinline__ float bfr(float x) {
    return __bfloat162float(__float2bfloat16(x));
}

// gelu(tanh approx) with per-op bf16 rounding, input already bf16-valued.
// jax.nn.gelu: 0.5 * x * (1 + tanh(sqrt(2/pi) * (x + 0.044715 * x**3)))
// x**3 lowered as rnd(rnd(x*x)*x); constants pre-rounded to bf16.
__device__ __forceinline__ float gelu_bf16_chain(float x) {
    float x2  = bfr(x * x);
    float x3  = bfr(x2 * x);
    float t   = bfr(bfr(0.044715f) * x3);
    float s   = bfr(x + t);
    float a   = bfr(bfr(0.7978845608028654f) * s);
    float th  = bfr(tanhf(a));
    float op  = bfr(1.0f + th);
    float cdf = bfr(0.5f * op);
    return bfr(x * cdf);
}

// expert id owning token-row row0 (tile assumed fully inside one expert;
// dataset groups are balanced multiples of BM)
__device__ __forceinline__ int expert_of(const int* counts, int row0) {
    int off = 0, e = 0;
#pragma unroll
    for (int i = 0; i < E_; i++) {
        if (row0 >= off) e = i;
        off += counts[i];
    }
    return e;
}

// ---------------------------------------------------------------------------
// Kernel 1: fused  g = x@w1[e]^T , u = x@w3[e]^T , h = gelu(g)*u  (bf16 out)
// grid: (H/BN, N/BM), 256 threads, warps 4(m) x 2(n), warp tile 32x32 (x2 mats)
// ---------------------------------------------------------------------------
__global__ __launch_bounds__(NTHREADS)
void moe_gemm13(const float* __restrict__ x,
                const float* __restrict__ w1,
                const float* __restrict__ w3,
                const int*   __restrict__ counts)
{
    __shared__ __align__(16) __nv_bfloat16 sA [2][BM * LD];
    __shared__ __align__(16) __nv_bfloat16 sB1[2][BN * LD];
    __shared__ __align__(16) __nv_bfloat16 sB3[2][BN * LD];
    __shared__ int s_e;

    const int tid  = threadIdx.x;
    const int lane = tid & 31;
    const int warp = tid >> 5;
    const int wm   = warp >> 1;   // 0..3
    const int wn   = warp & 1;    // 0..1
    const int row0 = blockIdx.y * BM;
    const int col0 = blockIdx.x * BN;

    if (tid == 0) s_e = expert_of(counts, row0);
    __syncthreads();
    const int e = s_e;

    const float* Ag  = x  + (size_t)row0 * D_;
    const float* B1g = w1 + (size_t)e * H_ * D_ + (size_t)col0 * D_;
    const float* B3g = w3 + (size_t)e * H_ * D_ + (size_t)col0 * D_;

    float cg[2][4][4] = {};
    float cu[2][4][4] = {};

    float4 ra[4], rb1[2], rb3[2];

    auto load_g = [&](int k0) {
#pragma unroll
        for (int i = 0; i < 4; i++) {
            int idx = tid + i * NTHREADS;
            int r = idx >> 3, c = (idx & 7) << 2;
            ra[i] = *reinterpret_cast<const float4*>(Ag + (size_t)r * D_ + k0 + c);
        }
#pragma unroll
        for (int i = 0; i < 2; i++) {
            int idx = tid + i * NTHREADS;
            int r = idx >> 3, c = (idx & 7) << 2;
            rb1[i] = *reinterpret_cast<const float4*>(B1g + (size_t)r * D_ + k0 + c);
            rb3[i] = *reinterpret_cast<const float4*>(B3g + (size_t)r * D_ + k0 + c);
        }
    };

    auto store_s = [&](int buf) {
#pragma unroll
        for (int i = 0; i < 4; i++) {
            int idx = tid + i * NTHREADS;
            int r = idx >> 3, c = (idx & 7) << 2;
            __nv_bfloat162* dst = reinterpret_cast<__nv_bfloat162*>(&sA[buf][r * LD + c]);
            dst[0] = __float22bfloat162_rn(make_float2(ra[i].x, ra[i].y));
            dst[1] = __float22bfloat162_rn(make_float2(ra[i].z, ra[i].w));
        }
#pragma unroll
        for (int i = 0; i < 2; i++) {
            int idx = tid + i * NTHREADS;
            int r = idx >> 3, c = (idx & 7) << 2;
            __nv_bfloat162* d1 = reinterpret_cast<__nv_bfloat162*>(&sB1[buf][r * LD + c]);
            d1[0] = __float22bfloat162_rn(make_float2(rb1[i].x, rb1[i].y));
            d1[1] = __float22bfloat162_rn(make_float2(rb1[i].z, rb1[i].w));
            __nv_bfloat162* d3 = reinterpret_cast<__nv_bfloat162*>(&sB3[buf][r * LD + c]);
            d3[0] = __float22bfloat162_rn(make_float2(rb3[i].x, rb3[i].y));
            d3[1] = __float22bfloat162_rn(make_float2(rb3[i].z, rb3[i].w));
        }
    };

    auto compute = [&](int buf) {
        const uint32_t baseA  = smem_u32(&sA [buf][0]);
        const uint32_t baseB1 = smem_u32(&sB1[buf][0]);
        const uint32_t baseB3 = smem_u32(&sB3[buf][0]);
#pragma unroll
        for (int kk = 0; kk < BK; kk += 16) {
            uint32_t a[2][4];
#pragma unroll
            for (int mi = 0; mi < 2; mi++) {
                int r = wm * 32 + mi * 16 + (lane & 15);
                int c = kk + ((lane >> 4) << 3);
                ldsm_x4(a[mi], baseA + (uint32_t)(r * LD + c) * 2u);
            }
#pragma unroll
            for (int ni = 0; ni < 4; ni++) {
                int l16 = lane & 15;
                int r = wn * 32 + ni * 8 + (l16 & 7);
                int c = kk + ((l16 >> 3) << 3);
                uint32_t b1[2], b3[2];
                ldsm_x2(b1, baseB1 + (uint32_t)(r * LD + c) * 2u);
                ldsm_x2(b3, baseB3 + (uint32_t)(r * LD + c) * 2u);
#pragma unroll
                for (int mi = 0; mi < 2; mi++) {
                    mma_bf16(cg[mi][ni], a[mi], b1);
                    mma_bf16(cu[mi][ni], a[mi], b3);
                }
            }
        }
    };

    const int NK = D_ / BK;  // 32
    load_g(0);
    store_s(0);
    __syncthreads();

    for (int kt = 0; kt < NK; kt++) {
        int cur = kt & 1;
        if (kt + 1 < NK) load_g((kt + 1) * BK);
        compute(cur);
        if (kt + 1 < NK) store_s(cur ^ 1);
        __syncthreads();
    }

    // epilogue: per-op bf16-rounded gelu(g) * u -> bf16 hbuf
    const int tr = lane >> 2;
    const int tc = (lane & 3) << 1;
#pragma unroll
    for (int mi = 0; mi < 2; mi++) {
#pragma unroll
        for (int ni = 0; ni < 4; ni++) {
#pragma unroll
            for (int rr = 0; rr < 2; rr++) {
                int r = row0 + wm * 32 + mi * 16 + tr + rr * 8;
                int c = col0 + wn * 32 + ni * 8 + tc;
                float g0 = bfr(cg[mi][ni][rr * 2 + 0]);
                float g1 = bfr(cg[mi][ni][rr * 2 + 1]);
                float u0 = bfr(cu[mi][ni][rr * 2 + 0]);
                float u1 = bfr(cu[mi][ni][rr * 2 + 1]);
                float h0 = gelu_bf16_chain(g0) * u0;
                float h1 = gelu_bf16_chain(g1) * u1;
                __nv_bfloat162 hv;
                hv.x = __float2bfloat16(h0);
                hv.y = __float2bfloat16(h1);
                *reinterpret_cast<__nv_bfloat162*>(&g_hbuf[(size_t)r * H_ + c]) = hv;
            }
        }
    }
}

// ---------------------------------------------------------------------------
// Kernel 2: out = h @ w2[e]^T   (bf16 x bf16 -> f32, output rounded via bf16)
// grid: (D/BN, N/BM)
// ---------------------------------------------------------------------------
__global__ __launch_bounds__(NTHREADS)
void moe_gemm2(const float* __restrict__ w2,
               const int*   __restrict__ counts,
               float*       __restrict__ out)
{
    __shared__ __align__(16) __nv_bfloat16 sA[2][BM * LD];
    __shared__ __align__(16) __nv_bfloat16 sB[2][BN * LD];
    __shared__ int s_e;

    const int tid  = threadIdx.x;
    const int lane = tid & 31;
    const int warp = tid >> 5;
    const int wm   = warp >> 1;
    const int wn   = warp & 1;
    const int row0 = blockIdx.y * BM;
    const int col0 = blockIdx.x * BN;

    if (tid == 0) s_e = expert_of(counts, row0);
    __syncthreads();
    const int e = s_e;

    const __nv_bfloat16* Ag = g_hbuf + (size_t)row0 * H_;
    const float*         Bg = w2 + (size_t)e * D_ * H_ + (size_t)col0 * H_;

    float co[2][4][4] = {};

    uint4  rA[2];
    float4 rB[2];

    auto load_g = [&](int k0) {
#pragma unroll
        for (int i = 0; i < 2; i++) {
            int idx = tid + i * NTHREADS;
            int r = idx >> 2, c = (idx & 3) << 3;   // 128 rows x 4 chunks of 8 bf16
            rA[i] = *reinterpret_cast<const uint4*>(Ag + (size_t)r * H_ + k0 + c);
        }
#pragma unroll
        for (int i = 0; i < 2; i++) {
            int idx = tid + i * NTHREADS;
            int r = idx >> 3, c = (idx & 7) << 2;   // 64 rows x 8 chunks of 4 f32
            rB[i] = *reinterpret_cast<const float4*>(Bg + (size_t)r * H_ + k0 + c);
        }
    };

    auto store_s = [&](int buf) {
#pragma unroll
        for (int i = 0; i < 2; i++) {
            int idx = tid + i * NTHREADS;
            int r = idx >> 2, c = (idx & 3) << 3;
            *reinterpret_cast<uint4*>(&sA[buf][r * LD + c]) = rA[i];
        }
#pragma unroll
        for (int i = 0; i < 2; i++) {
            int idx = tid + i * NTHREADS;
            int r = idx >> 3, c = (idx & 7) << 2;
            __nv_bfloat162* d = reinterpret_cast<__nv_bfloat162*>(&sB[buf][r * LD + c]);
            d[0] = __float22bfloat162_rn(make_float2(rB[i].x, rB[i].y));
            d[1] = __float22bfloat162_rn(make_float2(rB[i].z, rB[i].w));
        }
    };

    auto compute = [&](int buf) {
        const uint32_t baseA = smem_u32(&sA[buf][0]);
        const uint32_t baseB = smem_u32(&sB[buf][0]);
#pragma unroll
        for (int kk = 0; kk < BK; kk += 16) {
            uint32_t a[2][4];
#pragma unroll
            for (int mi = 0; mi < 2; mi++) {
                int r = wm * 32 + mi * 16 + (lane & 15);
                int c = kk + ((lane >> 4) << 3);
                ldsm_x4(a[mi], baseA + (uint32_t)(r * LD + c) * 2u);
            }
#pragma unroll
            for (int ni = 0; ni < 4; ni++) {
                int l16 = lane & 15;
                int r = wn * 32 + ni * 8 + (l16 & 7);
                int c = kk + ((l16 >> 3) << 3);
                uint32_t b[2];
                ldsm_x2(b, baseB + (uint32_t)(r * LD + c) * 2u);
#pragma unroll
                for (int mi = 0; mi < 2; mi++) {
                    mma_bf16(co[mi][ni], a[mi], b);
                }
            }
        }
    };

    const int NK = H_ / BK;  // 128
    load_g(0);
    store_s(0);
    __syncthreads();

    for (int kt = 0; kt < NK; kt++) {
        int cur = kt & 1;
        if (kt + 1 < NK) load_g((kt + 1) * BK);
        compute(cur);
        if (kt + 1 < NK) store_s(cur ^ 1);
        __syncthreads();
    }

    // epilogue: reference does ragged_dot(...).astype(f32) on a bf16 dot ->
    // round accumulator to bf16, store as f32.
    const int tr = lane >> 2;
    const int tc = (lane & 3) << 1;
#pragma unroll
    for (int mi = 0; mi < 2; mi++) {
#pragma unroll
        for (int ni = 0; ni < 4; ni++) {
#pragma unroll
            for (int rr = 0; rr < 2; rr++) {
                int r = row0 + wm * 32 + mi * 16 + tr + rr * 8;
                int c = col0 + wn * 32 + ni * 8 + tc;
                float2 ov;
                ov.x = bfr(co[mi][ni][rr * 2 + 0]);
                ov.y = bfr(co[mi][ni][rr * 2 + 1]);
                *reinterpret_cast<float2*>(&out[(size_t)r * D_ + c]) = ov;
            }
        }
    }
}

// ---------------------------------------------------------------------------
// launch
// ---------------------------------------------------------------------------
extern "C" void kernel_launch(void* const* d_in, const int* in_sizes, int n_in,
                              void* d_out, int out_size) {
    const float* x      = (const float*)d_in[0];
    const float* w1     = (const float*)d_in[1];
    const float* w2     = (const float*)d_in[2];
    const float* w3     = (const float*)d_in[3];
    const int*   counts = (const int*)d_in[4];
    float* out = (float*)d_out;

    dim3 g1(H_ / BN, N_ / BM);   // (64, 64)
    moe_gemm13<<<g1, NTHREADS>>>(x, w1, w3, counts);

    dim3 g2(D_ / BN, N_ / BM);   // (16, 64)
    moe_gemm2<<<g2, NTHREADS>>>(w2, counts, out);
}

// round 5
// speedup vs baseline: 1.0304x; 1.0304x over previous
#include <cuda_runtime.h>
#include <cuda_bf16.h>
#include <cstdint>
#include <cmath>

// Problem constants
#define E_ 8
#define D_ 1024
#define H_ 4096
#define N_ 8192

#define NTH 256
#define BK  64          // k-tile in bf16 elems
#define LDP 72          // padded smem row stride (bf16): 144B -> conflict-free LDSM

// bf16 copies of inputs (converted once per launch) + intermediate h
__device__ __nv_bfloat16 g_xb [(size_t)N_ * D_];
__device__ __nv_bfloat16 g_w1b[(size_t)E_ * H_ * D_];
__device__ __nv_bfloat16 g_w3b[(size_t)E_ * H_ * D_];
__device__ __nv_bfloat16 g_w2b[(size_t)E_ * D_ * H_];
__device__ __nv_bfloat16 g_hbuf[(size_t)N_ * H_];

// ---------------------------------------------------------------------------
// helpers
// ---------------------------------------------------------------------------
__device__ __forceinline__ uint32_t smem_u32(const void* p) {
    return (uint32_t)__cvta_generic_to_shared(p);
}
__device__ __forceinline__ void cp16(uint32_t saddr, const void* gaddr) {
    asm volatile("cp.async.cg.shared.global [%0], [%1], 16;\n"
                 :: "r"(saddr), "l"(gaddr));
}
__device__ __forceinline__ void cp_commit() {
    asm volatile("cp.async.commit_group;\n");
}
template <int N>
__device__ __forceinline__ void cp_wait() {
    asm volatile("cp.async.wait_group %0;\n" :: "n"(N));
}
__device__ __forceinline__ void ldsm_x4(uint32_t* r, uint32_t addr) {
    asm volatile("ldmatrix.sync.aligned.m8n8.x4.shared.b16 {%0,%1,%2,%3}, [%4];\n"
                 : "=r"(r[0]), "=r"(r[1]), "=r"(r[2]), "=r"(r[3]) : "r"(addr));
}
__device__ __forceinline__ void ldsm_x2(uint32_t* r, uint32_t addr) {
    asm volatile("ldmatrix.sync.aligned.m8n8.x2.shared.b16 {%0,%1}, [%2];\n"
                 : "=r"(r[0]), "=r"(r[1]) : "r"(addr));
}
__device__ __forceinline__ void mma_bf16(float* c, const uint32_t* a, const uint32_t* b) {
    asm volatile("mma.sync.aligned.m16n8k16.row.col.f32.bf16.bf16.f32 "
                 "{%0,%1,%2,%3}, {%4,%5,%6,%7}, {%8,%9}, {%0,%1,%2,%3};\n"
                 : "+f"(c[0]), "+f"(c[1]), "+f"(c[2]), "+f"(c[3])
                 : "r"(a[0]), "r"(a[1]), "r"(a[2]), "r"(a[3]),
                   "r"(b[0]), "r"(b[1]));
}
__device__ __forceinline__ float bfr(float x) {
    return __bfloat162float(__float2bfloat16(x));
}
__device__ __forceinline__ uint32_t pack_bf16(float a, float b) {
    __nv_bfloat162 v = __float22bfloat162_rn(make_float2(a, b));
    return *reinterpret_cast<uint32_t*>(&v);
}
__device__ __forceinline__ float gelu_bf16_chain(float x) {
    float x2  = bfr(x * x);
    float x3  = bfr(x2 * x);
    float t   = bfr(bfr(0.044715f) * x3);
    float s   = bfr(x + t);
    float a   = bfr(bfr(0.7978845608028654f) * s);
    float th  = bfr(tanhf(a));
    float op  = bfr(1.0f + th);
    float cdf = bfr(0.5f * op);
    return bfr(x * cdf);
}
__device__ __forceinline__ int expert_of(const int* counts, int row0) {
    int off = 0, e = 0;
#pragma unroll
    for (int i = 0; i < E_; i++) {
        if (row0 >= off) e = i;
        off += counts[i];
    }
    return e;
}

// ---------------------------------------------------------------------------
// fp32 -> bf16 convert (which: 0=x, 1=w1, 2=w3, 3=w2)
// ---------------------------------------------------------------------------
__global__ __launch_bounds__(NTH)
void cvt_bf16(const float* __restrict__ src, int which, int n4) {
    __nv_bfloat16* dst = (which == 0) ? g_xb
                       : (which == 1) ? g_w1b
                       : (which == 2) ? g_w3b : g_w2b;
    int i = blockIdx.x * NTH + threadIdx.x;
    if (i < n4) {
        float4 v = reinterpret_cast<const float4*>(src)[i];
        uint2 o;
        o.x = pack_bf16(v.x, v.y);
        o.y = pack_bf16(v.z, v.w);
        reinterpret_cast<uint2*>(dst)[i] = o;
    }
}

// ---------------------------------------------------------------------------
// GEMM 1: g = x@w1^T, u = x@w3^T, h = gelu(g)*u -> g_hbuf (bf16)
// CTA 128(M) x 128(N), BK=64, 2-stage cp.async.
// warps: 2(m) x 4(n), warp tile 64x32 per matrix.
// grid = (H/128, N_/128) = (32, 64)
// ---------------------------------------------------------------------------
#define TILE_B (128 * LDP * 2)        // 18432 bytes per 128x64 bf16 tile
#define ST1B   (3 * TILE_B)           // A + B1 + B3 per stage

__global__ __launch_bounds__(NTH, 1)
void moe_g1(const int* __restrict__ counts)
{
    extern __shared__ char sm[];
    __shared__ int s_e;

    const int tid  = threadIdx.x;
    const int lane = tid & 31;
    const int wid  = tid >> 5;
    const int wm   = wid >> 2;     // 0..1
    const int wn   = wid & 3;      // 0..3
    const int row0 = blockIdx.y * 128;
    const int col0 = blockIdx.x * 128;

    if (tid == 0) s_e = expert_of(counts, row0);
    __syncthreads();
    const int e = s_e;

    const __nv_bfloat16* Ag  = g_xb  + (size_t)row0 * D_;
    const __nv_bfloat16* B1g = g_w1b + ((size_t)e * H_ + col0) * D_;
    const __nv_bfloat16* B3g = g_w3b + ((size_t)e * H_ + col0) * D_;

    const uint32_t sb = smem_u32(sm);

    float cg[4][4][4] = {};
    float cu[4][4][4] = {};

    // stage loader: 128 rows x 8 chunks of 8 bf16 per tile = 1024 cp16 per tile
    auto load_stage = [&](int kt, int st) {
        const int k0 = kt * BK;
        const uint32_t s0 = sb + st * ST1B;
#pragma unroll
        for (int i = 0; i < 4; i++) {
            int id = tid + i * NTH;          // 0..1023
            int r = id >> 3, ch = id & 7;
            cp16(s0 + (uint32_t)(r * LDP + ch * 8) * 2u,
                 Ag + (size_t)r * D_ + k0 + ch * 8);
        }
#pragma unroll
        for (int i = 0; i < 4; i++) {
            int id = tid + i * NTH;
            int r = id >> 3, ch = id & 7;
            cp16(s0 + TILE_B + (uint32_t)(r * LDP + ch * 8) * 2u,
                 B1g + (size_t)r * D_ + k0 + ch * 8);
        }
#pragma unroll
        for (int i = 0; i < 4; i++) {
            int id = tid + i * NTH;
            int r = id >> 3, ch = id & 7;
            cp16(s0 + 2 * TILE_B + (uint32_t)(r * LDP + ch * 8) * 2u,
                 B3g + (size_t)r * D_ + k0 + ch * 8);
        }
    };

    auto compute = [&](int st) {
        const uint32_t aB  = sb + st * ST1B;
        const uint32_t b1B = aB + TILE_B;
        const uint32_t b3B = aB + 2 * TILE_B;
#pragma unroll
        for (int kk = 0; kk < 4; kk++) {
            const int kc = kk * 16;
            uint32_t a[4][4];
#pragma unroll
            for (int mi = 0; mi < 4; mi++) {
                int r = wm * 64 + mi * 16 + (lane & 15);
                int c = kc + ((lane >> 4) << 3);
                ldsm_x4(a[mi], aB + (uint32_t)(r * LDP + c) * 2u);
            }
#pragma unroll
            for (int ni = 0; ni < 4; ni++) {
                int l16 = lane & 15;
                int r = wn * 32 + ni * 8 + (l16 & 7);
                int c = kc + ((l16 >> 3) << 3);
                uint32_t b1[2], b3[2];
                ldsm_x2(b1, b1B + (uint32_t)(r * LDP + c) * 2u);
                ldsm_x2(b3, b3B + (uint32_t)(r * LDP + c) * 2u);
#pragma unroll
                for (int mi = 0; mi < 4; mi++) {
                    mma_bf16(cg[mi][ni], a[mi], b1);
                    mma_bf16(cu[mi][ni], a[mi], b3);
                }
            }
        }
    };

    const int NK = D_ / BK;   // 16
    load_stage(0, 0);
    cp_commit();

    for (int kt = 0; kt < NK; kt++) {
        const int cur = kt & 1;
        if (kt + 1 < NK) {
            load_stage(kt + 1, cur ^ 1);
            cp_commit();
            cp_wait<1>();
        } else {
            cp_wait<0>();
        }
        __syncthreads();
        compute(cur);
        __syncthreads();
    }

    // epilogue: bf16-rounded gelu(g)*u -> hbuf
    const int tr = lane >> 2;
    const int tc = (lane & 3) << 1;
#pragma unroll
    for (int mi = 0; mi < 4; mi++) {
#pragma unroll
        for (int ni = 0; ni < 4; ni++) {
#pragma unroll
            for (int rr = 0; rr < 2; rr++) {
                int r = row0 + wm * 64 + mi * 16 + rr * 8 + tr;
                int c = col0 + wn * 32 + ni * 8 + tc;
                float g0 = bfr(cg[mi][ni][rr * 2 + 0]);
                float g1 = bfr(cg[mi][ni][rr * 2 + 1]);
                float u0 = bfr(cu[mi][ni][rr * 2 + 0]);
                float u1 = bfr(cu[mi][ni][rr * 2 + 1]);
                uint32_t hv = pack_bf16(gelu_bf16_chain(g0) * u0,
                                        gelu_bf16_chain(g1) * u1);
                *reinterpret_cast<uint32_t*>(&g_hbuf[(size_t)r * H_ + c]) = hv;
            }
        }
    }
}

// ---------------------------------------------------------------------------
// GEMM 2: out = h @ w2^T. CTA 128x128, BK=64, 3-stage cp.async.
// grid = (D/128, N_/128) = (8, 64)
// ---------------------------------------------------------------------------
#define ST2B (2 * TILE_B)

__global__ __launch_bounds__(NTH, 1)
void moe_g2(const int* __restrict__ counts, float* __restrict__ out)
{
    extern __shared__ char sm[];
    __shared__ int s_e;

    const int tid  = threadIdx.x;
    const int lane = tid & 31;
    const int wid  = tid >> 5;
    const int wm   = wid >> 2;
    const int wn   = wid & 3;
    const int row0 = blockIdx.y * 128;
    const int col0 = blockIdx.x * 128;

    if (tid == 0) s_e = expert_of(counts, row0);
    __syncthreads();
    const int e = s_e;

    const __nv_bfloat16* Ag = g_hbuf + (size_t)row0 * H_;
    const __nv_bfloat16* Bg = g_w2b  + ((size_t)e * D_ + col0) * H_;

    const uint32_t sb = smem_u32(sm);

    float co[4][4][4] = {};

    auto load_stage = [&](int kt, int st) {
        const int k0 = kt * BK;
        const uint32_t s0 = sb + st * ST2B;
#pragma unroll
        for (int i = 0; i < 4; i++) {
            int id = tid + i * NTH;
            int r = id >> 3, ch = id & 7;
            cp16(s0 + (uint32_t)(r * LDP + ch * 8) * 2u,
                 Ag + (size_t)r * H_ + k0 + ch * 8);
        }
#pragma unroll
        for (int i = 0; i < 4; i++) {
            int id = tid + i * NTH;
            int r = id >> 3, ch = id & 7;
            cp16(s0 + TILE_B + (uint32_t)(r * LDP + ch * 8) * 2u,
                 Bg + (size_t)r * H_ + k0 + ch * 8);
        }
    };

    auto compute = [&](int st) {
        const uint32_t aB = sb + st * ST2B;
        const uint32_t bB = aB + TILE_B;
#pragma unroll
        for (int kk = 0; kk < 4; kk++) {
            const int kc = kk * 16;
            uint32_t a[4][4];
#pragma unroll
            for (int mi = 0; mi < 4; mi++) {
                int r = wm * 64 + mi * 16 + (lane & 15);
                int c = kc + ((lane >> 4) << 3);
                ldsm_x4(a[mi], aB + (uint32_t)(r * LDP + c) * 2u);
            }
#pragma unroll
            for (int ni = 0; ni < 4; ni++) {
                int l16 = lane & 15;
                int r = wn * 32 + ni * 8 + (l16 & 7);
                int c = kc + ((l16 >> 3) << 3);
                uint32_t b[2];
                ldsm_x2(b, bB + (uint32_t)(r * LDP + c) * 2u);
#pragma unroll
                for (int mi = 0; mi < 4; mi++) {
                    mma_bf16(co[mi][ni], a[mi], b);
                }
            }
        }
    };

    const int NK = H_ / BK;   // 64
    load_stage(0, 0);
    cp_commit();
    load_stage(1, 1);
    cp_commit();

    int cur = 0, pre = 2;
    for (int kt = 0; kt < NK; kt++) {
        if (kt + 2 < NK) {
            load_stage(kt + 2, pre);
            cp_commit();
            cp_wait<2>();
        } else {
            cp_wait<0>();
        }
        __syncthreads();
        compute(cur);
        __syncthreads();
        cur = (cur == 2) ? 0 : cur + 1;
        pre = (pre == 2) ? 0 : pre + 1;
    }

    // epilogue: round accumulator through bf16, store fp32
    const int tr = lane >> 2;
    const int tc = (lane & 3) << 1;
#pragma unroll
    for (int mi = 0; mi < 4; mi++) {
#pragma unroll
        for (int ni = 0; ni < 4; ni++) {
#pragma unroll
            for (int rr = 0; rr < 2; rr++) {
                int r = row0 + wm * 64 + mi * 16 + rr * 8 + tr;
                int c = col0 + wn * 32 + ni * 8 + tc;
                float2 ov;
                ov.x = bfr(co[mi][ni][rr * 2 + 0]);
                ov.y = bfr(co[mi][ni][rr * 2 + 1]);
                *reinterpret_cast<float2*>(&out[(size_t)r * D_ + c]) = ov;
            }
        }
    }
}

// ---------------------------------------------------------------------------
// launch
// ---------------------------------------------------------------------------
extern "C" void kernel_launch(void* const* d_in, const int* in_sizes, int n_in,
                              void* d_out, int out_size) {
    const float* x      = (const float*)d_in[0];
    const float* w1     = (const float*)d_in[1];
    const float* w2     = (const float*)d_in[2];
    const float* w3     = (const float*)d_in[3];
    const int*   counts = (const int*)d_in[4];
    float* out = (float*)d_out;

    // convert inputs to bf16
    {
        int n4x = (N_ * D_) / 4;            // 2,097,152
        int n4w = (E_ * H_ * D_) / 4;       // 8,388,608
        cvt_bf16<<<n4x / NTH, NTH>>>(x,  0, n4x);
        cvt_bf16<<<n4w / NTH, NTH>>>(w1, 1, n4w);
        cvt_bf16<<<n4w / NTH, NTH>>>(w3, 2, n4w);
        cvt_bf16<<<n4w / NTH, NTH>>>(w2, 3, n4w);
    }

    cudaFuncSetAttribute(moe_g1, cudaFuncAttributeMaxDynamicSharedMemorySize, 2 * ST1B);
    cudaFuncSetAttribute(moe_g2, cudaFuncAttributeMaxDynamicSharedMemorySize, 3 * ST2B);

    dim3 g1(H_ / 128, N_ / 128);   // (32, 64)
    moe_g1<<<g1, NTH, 2 * ST1B>>>(counts);

    dim3 g2(D_ / 128, N_ / 128);   // (8, 64)
    moe_g2<<<g2, NTH, 3 * ST2B>>>(counts, out);
}